// round 2
// baseline (speedup 1.0000x reference)
#include <cuda_runtime.h>
#include <cuda_bf16.h>

#define THICKNESS 0.00047f

__global__ void stvk_face_kernel(
    const float* __restrict__ pos,        // [V,3]
    const int* __restrict__ faces,        // [F,3] int32 (JAX downgrades int64 w/o x64)
    const float* __restrict__ dminv,      // [F,2,2] row-major
    const float* __restrict__ area,       // [F,1]
    const float* __restrict__ mu_p,       // [1]
    const float* __restrict__ lam_p,      // [1]
    float* __restrict__ per_vert,         // [V]
    float* __restrict__ loss,             // scalar or nullptr
    int F)
{
    int f = blockIdx.x * blockDim.x + threadIdx.x;
    float e = 0.0f;
    int i0 = 0, i1 = 0, i2 = 0;
    if (f < F) {
        i0 = __ldg(&faces[3 * f + 0]);
        i1 = __ldg(&faces[3 * f + 1]);
        i2 = __ldg(&faces[3 * f + 2]);

        float p0x = __ldg(&pos[3 * i0 + 0]);
        float p0y = __ldg(&pos[3 * i0 + 1]);
        float p0z = __ldg(&pos[3 * i0 + 2]);
        float p1x = __ldg(&pos[3 * i1 + 0]);
        float p1y = __ldg(&pos[3 * i1 + 1]);
        float p1z = __ldg(&pos[3 * i1 + 2]);
        float p2x = __ldg(&pos[3 * i2 + 0]);
        float p2y = __ldg(&pos[3 * i2 + 1]);
        float p2z = __ldg(&pos[3 * i2 + 2]);

        // Ds columns: d1 = v0 - v2, d2 = v1 - v2
        float d1x = p0x - p2x, d1y = p0y - p2y, d1z = p0z - p2z;
        float d2x = p1x - p2x, d2y = p1y - p2y, d2z = p1z - p2z;

        // Dm_inv[f] = [[a, b], [c, d]]
        float4 dm = __ldg((const float4*)(dminv) + f);
        float a = dm.x, b = dm.y, c = dm.z, d = dm.w;

        // Fg = Ds @ Dm_inv : col0 = d1*a + d2*c ; col1 = d1*b + d2*d
        float F0x = d1x * a + d2x * c;
        float F0y = d1y * a + d2y * c;
        float F0z = d1z * a + d2z * c;
        float F1x = d1x * b + d2x * d;
        float F1y = d1y * b + d2y * d;
        float F1z = d1z * b + d2z * d;

        // Green strain G = 0.5 (F^T F - I), symmetric 2x2
        float g00 = 0.5f * (F0x * F0x + F0y * F0y + F0z * F0z - 1.0f);
        float g01 = 0.5f * (F0x * F1x + F0y * F1y + F0z * F1z);
        float g11 = 0.5f * (F1x * F1x + F1y * F1y + F1z * F1z - 1.0f);
        float tr = g00 + g11;

        float mu = __ldg(mu_p);
        float lam = __ldg(lam_p);

        // S = mu*G + 0.5*lam*tr*I
        float s00 = mu * g00 + 0.5f * lam * tr;
        float s01 = mu * g01;
        float s11 = mu * g11 + 0.5f * lam * tr;

        // energy density = sum_ij S_ij G_ij (S,G symmetric)
        float ed = s00 * g00 + 2.0f * s01 * g01 + s11 * g11;

        e = __ldg(&area[f]) * THICKNESS * ed;

        float e3 = e * (1.0f / 3.0f);
        atomicAdd(&per_vert[i0], e3);
        atomicAdd(&per_vert[i1], e3);
        atomicAdd(&per_vert[i2], e3);
    }

    // block-reduce e, one global atomic per block for the loss
    float v = e;
    #pragma unroll
    for (int off = 16; off > 0; off >>= 1)
        v += __shfl_down_sync(0xFFFFFFFFu, v, off);

    __shared__ float smem[8];
    int lane = threadIdx.x & 31;
    int wid = threadIdx.x >> 5;
    if (lane == 0) smem[wid] = v;
    __syncthreads();
    if (wid == 0) {
        float w = (lane < (blockDim.x >> 5)) ? smem[lane] : 0.0f;
        #pragma unroll
        for (int off = 4; off > 0; off >>= 1)
            w += __shfl_down_sync(0xFFFFFFFFu, w, off);
        if (lane == 0 && loss != nullptr)
            atomicAdd(loss, w);
    }
}

extern "C" void kernel_launch(void* const* d_in, const int* in_sizes, int n_in,
                              void* d_out, int out_size) {
    const float* pos = (const float*)d_in[0];
    const int* faces = (const int*)d_in[1];
    const float* dminv = (const float*)d_in[2];
    const float* area = (const float*)d_in[3];
    const float* mu_p = (const float*)d_in[4];
    const float* lam_p = (const float*)d_in[5];

    int V = in_sizes[0] / 3;
    int F = in_sizes[1] / 3;

    float* out = (float*)d_out;
    // Flattened tuple order: loss scalar first, then per_vert[V].
    float* per_vert = out + (out_size - V);
    float* loss = (out_size > V) ? out : nullptr;

    cudaMemsetAsync(d_out, 0, (size_t)out_size * sizeof(float));

    int threads = 256;
    int blocks = (F + threads - 1) / threads;
    stvk_face_kernel<<<blocks, threads>>>(pos, faces, dminv, area, mu_p, lam_p,
                                          per_vert, loss, F);
}

// round 3
// speedup vs baseline: 1.0410x; 1.0410x over previous
#include <cuda_runtime.h>
#include <cuda_bf16.h>

#define THICKNESS 0.00047f

// Branchless parity-aligned vertex load: pos + 3*i is 8B-aligned iff i even.
// even: float2 (x,y) @ 3i, float z @ 3i+2
// odd : float  x    @ 3i, float2 (y,z) @ 3i+1 (8B-aligned)
__device__ __forceinline__ float3 load_vertex(const float* __restrict__ pos, int i) {
    bool even = (i & 1) == 0;
    const float* base = pos + 3u * (unsigned)i;
    const float2* p2 = (const float2*)(base + (even ? 0 : 1));
    const float*  p1 = base + (even ? 2 : 0);
    float2 ab = __ldg(p2);
    float  c  = __ldg(p1);
    float3 r;
    r.x = even ? ab.x : c;
    r.y = even ? ab.y : ab.x;
    r.z = even ? c    : ab.y;
    return r;
}

__global__ void stvk_face_kernel(
    const float* __restrict__ pos,        // [V,3]
    const int* __restrict__ faces,        // [F,3] int32
    const float* __restrict__ dminv,      // [F,2,2]
    const float* __restrict__ area,       // [F,1]
    const float* __restrict__ mu_p,       // [1]
    const float* __restrict__ lam_p,      // [1]
    float* __restrict__ per_vert,         // [V]
    float* __restrict__ loss,             // scalar or nullptr
    int F)
{
    int f = blockIdx.x * blockDim.x + threadIdx.x;
    float e = 0.0f;
    if (f < F) {
        // faces row: 12B at 4-alignment; 8-aligned iff f even. Same parity trick.
        bool feven = (f & 1) == 0;
        const int* frow = faces + 3u * (unsigned)f;
        const int2* f2p = (const int2*)(frow + (feven ? 0 : 1));
        const int*  f1p = frow + (feven ? 2 : 0);
        int2 fab = __ldg(f2p);
        int  fc  = __ldg(f1p);
        int i0 = feven ? fab.x : fc;
        int i1 = feven ? fab.y : fab.x;
        int i2 = feven ? fc    : fab.y;

        float3 p0 = load_vertex(pos, i0);
        float3 p1 = load_vertex(pos, i1);
        float3 p2 = load_vertex(pos, i2);

        // Ds columns: d1 = v0 - v2, d2 = v1 - v2
        float d1x = p0.x - p2.x, d1y = p0.y - p2.y, d1z = p0.z - p2.z;
        float d2x = p1.x - p2.x, d2y = p1.y - p2.y, d2z = p1.z - p2.z;

        float4 dm = __ldg((const float4*)(dminv) + f);
        float a = dm.x, b = dm.y, c = dm.z, d = dm.w;

        // Fg = Ds @ Dm_inv
        float F0x = d1x * a + d2x * c;
        float F0y = d1y * a + d2y * c;
        float F0z = d1z * a + d2z * c;
        float F1x = d1x * b + d2x * d;
        float F1y = d1y * b + d2y * d;
        float F1z = d1z * b + d2z * d;

        // Green strain (symmetric 2x2)
        float g00 = 0.5f * (F0x * F0x + F0y * F0y + F0z * F0z - 1.0f);
        float g01 = 0.5f * (F0x * F1x + F0y * F1y + F0z * F1z);
        float g11 = 0.5f * (F1x * F1x + F1y * F1y + F1z * F1z - 1.0f);
        float tr = g00 + g11;

        float mu = __ldg(mu_p);
        float lam = __ldg(lam_p);

        float s00 = mu * g00 + 0.5f * lam * tr;
        float s01 = mu * g01;
        float s11 = mu * g11 + 0.5f * lam * tr;

        float ed = s00 * g00 + 2.0f * s01 * g01 + s11 * g11;

        e = __ldg(&area[f]) * THICKNESS * ed;

        float e3 = e * (1.0f / 3.0f);
        atomicAdd(&per_vert[i0], e3);
        atomicAdd(&per_vert[i1], e3);
        atomicAdd(&per_vert[i2], e3);
    }

    // block-reduce e -> one loss atomic per block
    float v = e;
    #pragma unroll
    for (int off = 16; off > 0; off >>= 1)
        v += __shfl_down_sync(0xFFFFFFFFu, v, off);

    __shared__ float smem[8];
    int lane = threadIdx.x & 31;
    int wid = threadIdx.x >> 5;
    if (lane == 0) smem[wid] = v;
    __syncthreads();
    if (wid == 0) {
        float w = (lane < (blockDim.x >> 5)) ? smem[lane] : 0.0f;
        #pragma unroll
        for (int off = 4; off > 0; off >>= 1)
            w += __shfl_down_sync(0xFFFFFFFFu, w, off);
        if (lane == 0 && loss != nullptr)
            atomicAdd(loss, w);
    }
}

extern "C" void kernel_launch(void* const* d_in, const int* in_sizes, int n_in,
                              void* d_out, int out_size) {
    const float* pos = (const float*)d_in[0];
    const int* faces = (const int*)d_in[1];
    const float* dminv = (const float*)d_in[2];
    const float* area = (const float*)d_in[3];
    const float* mu_p = (const float*)d_in[4];
    const float* lam_p = (const float*)d_in[5];

    int V = in_sizes[0] / 3;
    int F = in_sizes[1] / 3;

    float* out = (float*)d_out;
    float* per_vert = out + (out_size - V);
    float* loss = (out_size > V) ? out : nullptr;

    cudaMemsetAsync(d_out, 0, (size_t)out_size * sizeof(float));

    int threads = 256;
    int blocks = (F + threads - 1) / threads;
    stvk_face_kernel<<<blocks, threads>>>(pos, faces, dminv, area, mu_p, lam_p,
                                          per_vert, loss, F);
}